// round 3
// baseline (speedup 1.0000x reference)
#include <cuda_runtime.h>
#include <math.h>
#include <stdint.h>

#define DIM   192
#define HEADS 6
#define HD    32
#define NWIN  1024          // 4 * 16 * 16
#define NQTOK 65536         // 1024 * 64  (== B*L)
#define NKVTOK 262144       // 1024 * 256
#define SCALE 0.17677669529663687f   // 32^-0.5

// ---------------- scratch (device globals; no runtime allocation) ----------------
__device__ float g_xn [(size_t)NQTOK * DIM];        // LN1 output, window order
__device__ float g_q  [(size_t)NQTOK * DIM];        // q projection, window order
__device__ float g_kv [(size_t)NKVTOK * 2 * DIM];   // k | v, window order
__device__ float g_ao [(size_t)NQTOK * DIM];        // attention output, window order
__device__ float g_x1 [(size_t)NQTOK * DIM];        // x after first residual, natural order
__device__ float g_ln2[(size_t)NQTOK * DIM];        // LN2 output
__device__ float g_h  [(size_t)NQTOK * 4 * DIM];    // gelu(fc1) output

// ---------------- LayerNorm (one token per block, 192 threads) ----------------
// MODE 0: read x in natural order, write in 8x8-window-partition order.
// MODE 1: natural in, natural out.
template<int MODE>
__global__ __launch_bounds__(192) void ln_kernel(
    const float* __restrict__ x, const float* __restrict__ w,
    const float* __restrict__ b, float* __restrict__ out)
{
    int tok = blockIdx.x;
    int tid = threadIdx.x;
    int in_row, out_row;
    if (MODE == 0) {
        int win = tok >> 6, t = tok & 63;
        int bb = win >> 8, wi = win & 255;
        int wr = wi >> 4,  wc = wi & 15;
        int r  = t  >> 3,  c  = t  & 7;
        in_row  = bb * 16384 + (wr * 8 + r) * 128 + (wc * 8 + c);
        out_row = tok;
    } else {
        in_row = out_row = tok;
    }
    float v = x[(size_t)in_row * DIM + tid];
    float s1 = v, s2 = v * v;
    #pragma unroll
    for (int off = 16; off; off >>= 1) {
        s1 += __shfl_xor_sync(0xffffffffu, s1, off);
        s2 += __shfl_xor_sync(0xffffffffu, s2, off);
    }
    __shared__ float red[12];
    int warp = tid >> 5, lane = tid & 31;
    if (lane == 0) { red[warp] = s1; red[6 + warp] = s2; }
    __syncthreads();
    if (tid == 0) {
        float a = 0.f, c2 = 0.f;
        #pragma unroll
        for (int i = 0; i < 6; i++) { a += red[i]; c2 += red[6 + i]; }
        red[0] = a; red[6] = c2;
    }
    __syncthreads();
    float mean = red[0] * (1.0f / 192.0f);
    float var  = red[6] * (1.0f / 192.0f) - mean * mean;
    float rstd = rsqrtf(var + 1e-5f);
    out[(size_t)out_row * DIM + tid] = (v - mean) * rstd * w[tid] + b[tid];
}

// ---------------- Generic tiled SGEMM: C = A @ W^T + bias, with epilogues ----------
// W is (N, K) row-major. A rows row-major stride K.
// MODE 0: plain A, plain store
// MODE 1: A rows gathered through 16x16 window partition of x2, plain store
// MODE 2: plain A (window order), epilogue: + add[nat_row] (shortcut), store at
//         window-reversed natural row
// MODE 3: plain A, epilogue exact gelu, plain store
// MODE 4: plain A, epilogue + add[row], plain store
template<int MODE, int N, int K>
__global__ __launch_bounds__(256) void gemm_kernel(
    const float* __restrict__ A, const float* __restrict__ W,
    const float* __restrict__ bias, float* __restrict__ C,
    const float* __restrict__ add)
{
    constexpr int BM = 128, BN = 64, BK = 16;
    __shared__ float As[BK][BM + 4];
    __shared__ float Bs[BK][BN + 4];

    int tid = threadIdx.x;
    int mb = blockIdx.x * BM, nb = blockIdx.y * BN;

    int r0 = tid >> 2;
    int kq = (tid & 3) * 4;

    int arow0 = mb + r0;
    int arow1 = mb + r0 + 64;
    int src0, src1;
    if (MODE == 1) {
        // window-order kv token -> natural x2 row
        int win = arow0 >> 8, t = arow0 & 255;
        int bb = win >> 8, wi = win & 255;
        int wr = wi >> 4,  wc = wi & 15;
        int rr = t  >> 4,  cc = t  & 15;
        src0 = bb * 65536 + (wr * 16 + rr) * 256 + (wc * 16 + cc);
        win = arow1 >> 8; t = arow1 & 255;
        bb = win >> 8; wi = win & 255;
        wr = wi >> 4;  wc = wi & 15;
        rr = t  >> 4;  cc = t  & 15;
        src1 = bb * 65536 + (wr * 16 + rr) * 256 + (wc * 16 + cc);
    } else {
        src0 = arow0; src1 = arow1;
    }
    const float* ap0 = A + (size_t)src0 * K + kq;
    const float* ap1 = A + (size_t)src1 * K + kq;
    int bn = tid >> 2;
    const float* wp = W + (size_t)(nb + bn) * K + kq;

    float acc[8][4];
    #pragma unroll
    for (int i = 0; i < 8; i++)
        #pragma unroll
        for (int j = 0; j < 4; j++) acc[i][j] = 0.f;

    int ty = tid >> 4, tx = tid & 15;

    for (int k0 = 0; k0 < K; k0 += BK) {
        float4 a0 = *(const float4*)(ap0 + k0);
        float4 a1 = *(const float4*)(ap1 + k0);
        float4 bv = *(const float4*)(wp + k0);
        As[kq + 0][r0] = a0.x; As[kq + 1][r0] = a0.y;
        As[kq + 2][r0] = a0.z; As[kq + 3][r0] = a0.w;
        As[kq + 0][r0 + 64] = a1.x; As[kq + 1][r0 + 64] = a1.y;
        As[kq + 2][r0 + 64] = a1.z; As[kq + 3][r0 + 64] = a1.w;
        Bs[kq + 0][bn] = bv.x; Bs[kq + 1][bn] = bv.y;
        Bs[kq + 2][bn] = bv.z; Bs[kq + 3][bn] = bv.w;
        __syncthreads();
        #pragma unroll
        for (int k = 0; k < BK; k++) {
            float ra[8], rb[4];
            *(float4*)&ra[0] = *(const float4*)&As[k][ty * 8];
            *(float4*)&ra[4] = *(const float4*)&As[k][ty * 8 + 4];
            *(float4*)&rb[0] = *(const float4*)&Bs[k][tx * 4];
            #pragma unroll
            for (int i = 0; i < 8; i++)
                #pragma unroll
                for (int j = 0; j < 4; j++)
                    acc[i][j] += ra[i] * rb[j];
        }
        __syncthreads();
    }

    float4 bb4 = *(const float4*)(bias + nb + tx * 4);
    #pragma unroll
    for (int i = 0; i < 8; i++) {
        int row = mb + ty * 8 + i;
        int col = nb + tx * 4;
        float4 o;
        o.x = acc[i][0] + bb4.x; o.y = acc[i][1] + bb4.y;
        o.z = acc[i][2] + bb4.z; o.w = acc[i][3] + bb4.w;
        if (MODE == 2) {
            int win = row >> 6, t = row & 63;
            int bI = win >> 8, wi = win & 255;
            int wr = wi >> 4,  wc = wi & 15;
            int rr = t  >> 3,  cc = t  & 7;
            int nat = bI * 16384 + (wr * 8 + rr) * 128 + (wc * 8 + cc);
            const float4 s = *(const float4*)(add + (size_t)nat * DIM + col);
            o.x += s.x; o.y += s.y; o.z += s.z; o.w += s.w;
            *(float4*)(C + (size_t)nat * DIM + col) = o;
        } else if (MODE == 3) {
            o.x = 0.5f * o.x * (1.0f + erff(o.x * 0.70710678118654752f));
            o.y = 0.5f * o.y * (1.0f + erff(o.y * 0.70710678118654752f));
            o.z = 0.5f * o.z * (1.0f + erff(o.z * 0.70710678118654752f));
            o.w = 0.5f * o.w * (1.0f + erff(o.w * 0.70710678118654752f));
            *(float4*)(C + (size_t)row * N + col) = o;
        } else if (MODE == 4) {
            const float4 s = *(const float4*)(add + (size_t)row * N + col);
            o.x += s.x; o.y += s.y; o.z += s.z; o.w += s.w;
            *(float4*)(C + (size_t)row * N + col) = o;
        } else {
            *(float4*)(C + (size_t)row * N + col) = o;
        }
    }
}

// ---------------- Attention: one block per (window, head) ----------------
// q (64x32, pre-scaled), kT (32x256 padded), v (256x32), S (64x256), bias (529)
// all in shared. 256 threads, warp w owns score rows w*8..w*8+7 end-to-end.
#define KT_STRIDE 260
#define ATTN_SMEM_FLOATS (2048 + 32 * KT_STRIDE + 8192 + 16384 + 532)

__global__ __launch_bounds__(256) void attn_kernel(const float* __restrict__ rel_bias)
{
    extern __shared__ float sm[];
    float* sQ  = sm;                      // 64*32   = 2048
    float* sKT = sm + 2048;               // 32*260  = 8320
    float* sV  = sKT + 32 * KT_STRIDE;    // 256*32  = 8192
    float* sS  = sV + 8192;               // 64*256  = 16384
    float* sB  = sS + 16384;              // 529 (+pad)

    int win = blockIdx.x, h = blockIdx.y;
    int tid = threadIdx.x;

    for (int r = tid; r < 529; r += 256) sB[r] = rel_bias[r * HEADS + h];

    const float* qb = g_q + (size_t)win * 64 * DIM + h * HD;
    for (int idx = tid; idx < 64 * 32; idx += 256) {
        int i = idx >> 5, d = idx & 31;
        sQ[idx] = qb[i * DIM + d] * SCALE;
    }
    const float* kb = g_kv + (size_t)win * 256 * (2 * DIM) + h * HD;
    const float* vb = kb + DIM;
    for (int idx = tid; idx < 256 * 32; idx += 256) {
        int j = idx >> 5, d = idx & 31;
        sKT[d * KT_STRIDE + j] = kb[(size_t)j * (2 * DIM) + d];
        sV[idx]                = vb[(size_t)j * (2 * DIM) + d];
    }
    __syncthreads();

    int warp = tid >> 5, lane = tid & 31;

    // ---- S = (q*scale) @ k^T + bias : warp w -> rows w*8..+7, lane -> j = lane*8..+7
    for (int r = 0; r < 8; r++) {
        int i = warp * 8 + r;
        float acc[8] = {0.f, 0.f, 0.f, 0.f, 0.f, 0.f, 0.f, 0.f};
        #pragma unroll
        for (int kk = 0; kk < 32; kk++) {
            float qv = sQ[i * 32 + kk];
            float4 k0 = *(const float4*)&sKT[kk * KT_STRIDE + lane * 8];
            float4 k1 = *(const float4*)&sKT[kk * KT_STRIDE + lane * 8 + 4];
            acc[0] += qv * k0.x; acc[1] += qv * k0.y;
            acc[2] += qv * k0.z; acc[3] += qv * k0.w;
            acc[4] += qv * k1.x; acc[5] += qv * k1.y;
            acc[6] += qv * k1.z; acc[7] += qv * k1.w;
        }
        int r1 = i >> 3, c1 = i & 7;
        #pragma unroll
        for (int u = 0; u < 8; u++) {
            int j = lane * 8 + u;
            int ridx = (r1 - (j >> 4) + 15) * 23 + (c1 - (j & 15) + 15);
            sS[i * 256 + j] = acc[u] + sB[ridx];
        }
    }
    __syncwarp();

    // ---- row softmax (warp-local rows)
    for (int r = 0; r < 8; r++) {
        int i = warp * 8 + r;
        float* row = sS + i * 256;
        float vals[8];
        float m = -1e30f;
        #pragma unroll
        for (int u = 0; u < 8; u++) { vals[u] = row[lane + u * 32]; m = fmaxf(m, vals[u]); }
        #pragma unroll
        for (int off = 16; off; off >>= 1) m = fmaxf(m, __shfl_xor_sync(0xffffffffu, m, off));
        float s = 0.f;
        #pragma unroll
        for (int u = 0; u < 8; u++) { vals[u] = __expf(vals[u] - m); s += vals[u]; }
        #pragma unroll
        for (int off = 16; off; off >>= 1) s += __shfl_xor_sync(0xffffffffu, s, off);
        float inv = 1.0f / s;
        #pragma unroll
        for (int u = 0; u < 8; u++) row[lane + u * 32] = vals[u] * inv;
    }
    __syncwarp();

    // ---- O = P @ v : warp w rows, lane -> output dim d
    float acc[8] = {0.f, 0.f, 0.f, 0.f, 0.f, 0.f, 0.f, 0.f};
    int i0 = warp * 8;
    for (int j4 = 0; j4 < 64; j4++) {
        int j = j4 * 4;
        float v0 = sV[(j + 0) * 32 + lane];
        float v1 = sV[(j + 1) * 32 + lane];
        float v2 = sV[(j + 2) * 32 + lane];
        float v3 = sV[(j + 3) * 32 + lane];
        #pragma unroll
        for (int rr = 0; rr < 8; rr++) {
            float4 p = *(const float4*)&sS[(i0 + rr) * 256 + j];
            acc[rr] += p.x * v0 + p.y * v1 + p.z * v2 + p.w * v3;
        }
    }
    float* ob = g_ao + (size_t)win * 64 * DIM + h * HD + lane;
    #pragma unroll
    for (int rr = 0; rr < 8; rr++)
        ob[(size_t)(i0 + rr) * DIM] = acc[rr];
}

// ---------------- launch ----------------
extern "C" void kernel_launch(void* const* d_in, const int* in_sizes, int n_in,
                              void* d_out, int out_size)
{
    const float* x     = (const float*)d_in[0];
    const float* x2    = (const float*)d_in[1];
    const float* n1w   = (const float*)d_in[2];
    const float* n1b   = (const float*)d_in[3];
    const float* qkvw  = (const float*)d_in[4];
    const float* qkvb  = (const float*)d_in[5];
    const float* qkv2w = (const float*)d_in[6];
    const float* qkv2b = (const float*)d_in[7];
    const float* relb  = (const float*)d_in[8];
    const float* projw = (const float*)d_in[9];
    const float* projb = (const float*)d_in[10];
    const float* n2w   = (const float*)d_in[11];
    const float* n2b   = (const float*)d_in[12];
    const float* fc1w  = (const float*)d_in[13];
    const float* fc1b  = (const float*)d_in[14];
    const float* fc2w  = (const float*)d_in[15];
    const float* fc2b  = (const float*)d_in[16];
    float* out = (float*)d_out;

    float *p_xn, *p_q, *p_kv, *p_ao, *p_x1, *p_ln2, *p_h;
    cudaGetSymbolAddress((void**)&p_xn,  g_xn);
    cudaGetSymbolAddress((void**)&p_q,   g_q);
    cudaGetSymbolAddress((void**)&p_kv,  g_kv);
    cudaGetSymbolAddress((void**)&p_ao,  g_ao);
    cudaGetSymbolAddress((void**)&p_x1,  g_x1);
    cudaGetSymbolAddress((void**)&p_ln2, g_ln2);
    cudaGetSymbolAddress((void**)&p_h,   g_h);

    const int attn_smem = ATTN_SMEM_FLOATS * (int)sizeof(float);
    cudaFuncSetAttribute(attn_kernel, cudaFuncAttributeMaxDynamicSharedMemorySize, attn_smem);

    // 1. LN1 + window partition
    ln_kernel<0><<<NQTOK, 192>>>(x, n1w, n1b, p_xn);
    // 2. q projection (window order)
    gemm_kernel<0, 192, 192><<<dim3(512, 3), 256>>>(p_xn, qkvw, qkvb, p_q, nullptr);
    // 3. kv projection (gather x2 through 16x16 window partition)
    gemm_kernel<1, 384, 192><<<dim3(2048, 6), 256>>>(x2, qkv2w, qkv2b, p_kv, nullptr);
    // 4. windowed cross attention
    attn_kernel<<<dim3(NWIN, HEADS), 256, attn_smem>>>(relb);
    // 5. output projection + shortcut + window reverse -> natural order
    gemm_kernel<2, 192, 192><<<dim3(512, 3), 256>>>(p_ao, projw, projb, p_x1, x);
    // 6. LN2
    ln_kernel<1><<<NQTOK, 192>>>(p_x1, n2w, n2b, p_ln2);
    // 7. fc1 + gelu
    gemm_kernel<3, 768, 192><<<dim3(512, 12), 256>>>(p_ln2, fc1w, fc1b, p_h, nullptr);
    // 8. fc2 + residual -> output
    gemm_kernel<4, 192, 768><<<dim3(512, 3), 256>>>(p_h, fc2w, fc2b, out, p_x1);
}